// round 2
// baseline (speedup 1.0000x reference)
#include <cuda_runtime.h>
#include <math.h>

#define HEADS 32
#define S_LEN 2048
#define BATCH 2
#define HID   4096
#define DH    128
#define NROWS (BATCH*S_LEN)   // 4096

// ---------------- scratch (static __device__, no allocs) ----------------
__device__ float g_Q[(size_t)BATCH*HEADS*S_LEN*DH];   // 64 MB
__device__ float g_K[(size_t)BATCH*HEADS*S_LEN*DH];   // 64 MB
__device__ float g_V[(size_t)BATCH*HEADS*S_LEN*DH];   // 64 MB
__device__ float g_Ctx[(size_t)NROWS*HID];            // 64 MB
__device__ float g_cos[S_LEN*64];
__device__ float g_sin[S_LEN*64];

// ---------------- GEMM: C[M,N] = A[M,K] @ B[N,K]^T  (both row-major, K contiguous)
// M=N=K=4096.  splitHeads=1 scatters output into [B,heads,S,Dh].
__global__ __launch_bounds__(256) void gemm_nt(
    const float* __restrict__ A, const float* __restrict__ B,
    float* __restrict__ C, int splitHeads)
{
    __shared__ float As[16][132];
    __shared__ float Bs[16][132];

    const int t  = threadIdx.x;
    const int bm = blockIdx.y * 128;
    const int bn = blockIdx.x * 128;
    const int lr = t >> 2;          // 0..63
    const int lk = (t & 3) << 2;    // 0,4,8,12
    const int tx = t & 15, ty = t >> 4;

    const float* Aptr = A + (size_t)(bm + lr) * HID + lk;
    const float* Bptr = B + (size_t)(bn + lr) * HID + lk;

    float acc[8][8];
    #pragma unroll
    for (int i = 0; i < 8; i++)
        #pragma unroll
        for (int j = 0; j < 8; j++) acc[i][j] = 0.f;

    for (int k0 = 0; k0 < HID; k0 += 16) {
        float4 a0 = *(const float4*)(Aptr + k0);
        float4 a1 = *(const float4*)(Aptr + k0 + (size_t)64*HID);
        float4 b0 = *(const float4*)(Bptr + k0);
        float4 b1 = *(const float4*)(Bptr + k0 + (size_t)64*HID);
        __syncthreads();
        As[lk+0][lr]    = a0.x; As[lk+1][lr]    = a0.y; As[lk+2][lr]    = a0.z; As[lk+3][lr]    = a0.w;
        As[lk+0][lr+64] = a1.x; As[lk+1][lr+64] = a1.y; As[lk+2][lr+64] = a1.z; As[lk+3][lr+64] = a1.w;
        Bs[lk+0][lr]    = b0.x; Bs[lk+1][lr]    = b0.y; Bs[lk+2][lr]    = b0.z; Bs[lk+3][lr]    = b0.w;
        Bs[lk+0][lr+64] = b1.x; Bs[lk+1][lr+64] = b1.y; Bs[lk+2][lr+64] = b1.z; Bs[lk+3][lr+64] = b1.w;
        __syncthreads();
        #pragma unroll
        for (int kk = 0; kk < 16; kk++) {
            float4 av0 = *(const float4*)&As[kk][ty*8];
            float4 av1 = *(const float4*)&As[kk][ty*8+4];
            float4 bv0 = *(const float4*)&Bs[kk][tx*8];
            float4 bv1 = *(const float4*)&Bs[kk][tx*8+4];
            float ar[8] = {av0.x,av0.y,av0.z,av0.w,av1.x,av1.y,av1.z,av1.w};
            float br[8] = {bv0.x,bv0.y,bv0.z,bv0.w,bv1.x,bv1.y,bv1.z,bv1.w};
            #pragma unroll
            for (int i = 0; i < 8; i++)
                #pragma unroll
                for (int j = 0; j < 8; j++)
                    acc[i][j] += ar[i]*br[j];
        }
    }

    #pragma unroll
    for (int i = 0; i < 8; i++) {
        int row = bm + ty*8 + i;
        int col = bn + tx*8;
        float* outp;
        if (splitHeads) {
            int b = row >> 11;            // row / 2048
            int s = row & (S_LEN-1);
            int h = col >> 7;             // col / 128
            int d = col & 127;
            outp = C + ((((size_t)(b*HEADS + h))*S_LEN + s) << 7) + d;
        } else {
            outp = C + (size_t)row*HID + col;
        }
        float4 v0 = make_float4(acc[i][0],acc[i][1],acc[i][2],acc[i][3]);
        float4 v1 = make_float4(acc[i][4],acc[i][5],acc[i][6],acc[i][7]);
        *(float4*)outp     = v0;
        *(float4*)(outp+4) = v1;
    }
}

// ---------------- RoPE ----------------
__global__ void rope_table_kernel(const int* __restrict__ pos_ids)
{
    int idx = blockIdx.x*blockDim.x + threadIdx.x;   // 0 .. S_LEN*64-1
    int i = idx & 63;
    int s = idx >> 6;
    float pos = (float)pos_ids[s];
    double invf = pow(10000.0, -(double)(2*i) / 128.0);
    float ang = pos * (float)invf;   // fp32 product, matching reference rounding
    float sn, cs;
    sincosf(ang, &sn, &cs);
    g_cos[idx] = cs;
    g_sin[idx] = sn;
}

__global__ void rope_apply_kernel()
{
    int idx = blockIdx.x*blockDim.x + threadIdx.x;   // 0 .. B*H*S*64-1
    int i  = idx & 63;
    int s  = (idx >> 6) & (S_LEN-1);
    int bh = idx >> 17;
    float cs = g_cos[(s<<6) + i];
    float sn = g_sin[(s<<6) + i];
    size_t base = (((size_t)bh * S_LEN + s) << 7) + i;
    float q0 = g_Q[base], q1 = g_Q[base+64];
    g_Q[base]    = q0*cs - q1*sn;
    g_Q[base+64] = q1*cs + q0*sn;
    float k0 = g_K[base], k1 = g_K[base+64];
    g_K[base]    = k0*cs - k1*sn;
    g_K[base+64] = k1*cs + k0*sn;
}

// ---------------- Flash attention (fp32, causal) ----------------
// Block: (qtile, head, batch).  64 q rows x 64 kv cols per iter, Dh=128.
// 256 threads: QK phase 16x16 grid of 4x4; PV phase same rows, 8 cols each.
#define AT_SMEM_FLOATS (2*DH*68 + 64*DH + 64*68)

__global__ __launch_bounds__(256, 1) void attn_kernel(
    const float* __restrict__ Q, const float* __restrict__ Km,
    const float* __restrict__ V, float* __restrict__ Out)
{
    extern __shared__ float smf[];
    float* Qt = smf;                 // [128][68]  (k-major, transposed)
    float* Kt = Qt + DH*68;          // [128][68]
    float* Vs = Kt + DH*68;          // [64][128]
    float* Ps = Vs + 64*DH;          // [64][68]

    const int qt = blockIdx.x, h = blockIdx.y, b = blockIdx.z;
    const int t  = threadIdx.x;
    const int tx = t & 15, ty = t >> 4;
    const size_t bh = (size_t)b*HEADS + h;

    const float* Qg = Q + (bh*S_LEN + (size_t)qt*64)*DH;
    #pragma unroll
    for (int p = 0; p < 32; p++) {
        int e = p*256 + t;
        Qt[(e & 127)*68 + (e >> 7)] = Qg[e];
    }

    float m_i[4], l_i[4], o[4][8];
    #pragma unroll
    for (int i = 0; i < 4; i++) {
        m_i[i] = -1e30f; l_i[i] = 0.f;
        #pragma unroll
        for (int j = 0; j < 8; j++) o[i][j] = 0.f;
    }

    for (int kt = 0; kt <= qt; kt++) {
        const float* Kg = Km + (bh*S_LEN + (size_t)kt*64)*DH;
        const float* Vg = V  + (bh*S_LEN + (size_t)kt*64)*DH;
        __syncthreads();   // previous iter's PV reads done
        #pragma unroll
        for (int p = 0; p < 32; p++) {
            int e = p*256 + t;
            Kt[(e & 127)*68 + (e >> 7)] = Kg[e];
        }
        {
            const float4* Vg4 = (const float4*)Vg;
            float4* Vs4 = (float4*)Vs;
            #pragma unroll
            for (int p = 0; p < 8; p++)
                Vs4[p*256 + t] = Vg4[p*256 + t];
        }
        __syncthreads();

        // --- S = Q K^T (4x4 per thread) ---
        float sacc[4][4];
        #pragma unroll
        for (int i = 0; i < 4; i++)
            #pragma unroll
            for (int j = 0; j < 4; j++) sacc[i][j] = 0.f;

        #pragma unroll 8
        for (int kk = 0; kk < DH; kk++) {
            float4 qv = *(const float4*)&Qt[kk*68 + ty*4];
            float4 kv = *(const float4*)&Kt[kk*68 + tx*4];
            float qa[4] = {qv.x,qv.y,qv.z,qv.w};
            float ka[4] = {kv.x,kv.y,kv.z,kv.w};
            #pragma unroll
            for (int i = 0; i < 4; i++)
                #pragma unroll
                for (int j = 0; j < 4; j++)
                    sacc[i][j] += qa[i]*ka[j];
        }

        // --- online softmax update ---
        const float scale = 0.08838834764831845f;  // 1/sqrt(128)
        const bool diag = (kt == qt);
        #pragma unroll
        for (int i = 0; i < 4; i++) {
            int r = ty*4 + i;
            float mx = -1e30f;
            #pragma unroll
            for (int j = 0; j < 4; j++) {
                float sv = sacc[i][j]*scale;
                if (diag && (tx*4 + j > r)) sv = -1e30f;
                sacc[i][j] = sv;
                mx = fmaxf(mx, sv);
            }
            mx = fmaxf(mx, __shfl_xor_sync(0xffffffffu, mx, 1));
            mx = fmaxf(mx, __shfl_xor_sync(0xffffffffu, mx, 2));
            mx = fmaxf(mx, __shfl_xor_sync(0xffffffffu, mx, 4));
            mx = fmaxf(mx, __shfl_xor_sync(0xffffffffu, mx, 8));
            float mnew = fmaxf(m_i[i], mx);
            float corr = __expf(m_i[i] - mnew);
            m_i[i] = mnew;
            float sum = 0.f;
            #pragma unroll
            for (int j = 0; j < 4; j++) {
                float pv = __expf(sacc[i][j] - mnew);
                Ps[r*68 + tx*4 + j] = pv;
                sum += pv;
            }
            sum += __shfl_xor_sync(0xffffffffu, sum, 1);
            sum += __shfl_xor_sync(0xffffffffu, sum, 2);
            sum += __shfl_xor_sync(0xffffffffu, sum, 4);
            sum += __shfl_xor_sync(0xffffffffu, sum, 8);
            l_i[i] = l_i[i]*corr + sum;
            #pragma unroll
            for (int jj = 0; jj < 8; jj++) o[i][jj] *= corr;
        }
        __syncthreads();   // Ps complete before PV

        // --- O += P V (4 rows x 8 cols per thread) ---
        #pragma unroll 4
        for (int j = 0; j < 64; j++) {
            float4 v0 = *(const float4*)&Vs[j*DH + tx*8];
            float4 v1 = *(const float4*)&Vs[j*DH + tx*8 + 4];
            #pragma unroll
            for (int i = 0; i < 4; i++) {
                float pv = Ps[(ty*4+i)*68 + j];
                o[i][0] += pv*v0.x; o[i][1] += pv*v0.y;
                o[i][2] += pv*v0.z; o[i][3] += pv*v0.w;
                o[i][4] += pv*v1.x; o[i][5] += pv*v1.y;
                o[i][6] += pv*v1.z; o[i][7] += pv*v1.w;
            }
        }
    }

    // --- normalize + write context [B,S,H] ---
    #pragma unroll
    for (int i = 0; i < 4; i++) {
        float inv = 1.0f / l_i[i];
        int srow = qt*64 + ty*4 + i;
        float* op = Out + ((size_t)b*S_LEN + srow)*HID + h*DH + tx*8;
        float4 r0 = make_float4(o[i][0]*inv, o[i][1]*inv, o[i][2]*inv, o[i][3]*inv);
        float4 r1 = make_float4(o[i][4]*inv, o[i][5]*inv, o[i][6]*inv, o[i][7]*inv);
        *(float4*)op     = r0;
        *(float4*)(op+4) = r1;
    }
}

// ---------------- launch ----------------
extern "C" void kernel_launch(void* const* d_in, const int* in_sizes, int n_in,
                              void* d_out, int out_size)
{
    const float* hs = (const float*)d_in[0];
    const float* Wq = (const float*)d_in[1];
    const float* Wk = (const float*)d_in[2];
    const float* Wv = (const float*)d_in[3];
    const float* Wo = (const float*)d_in[4];
    // d_in[5] = attn_mask (causal; applied analytically)
    const int* pos  = (const int*)d_in[6];
    float* out = (float*)d_out;

    float *Qp, *Kp, *Vp, *Cp;
    cudaGetSymbolAddress((void**)&Qp, g_Q);
    cudaGetSymbolAddress((void**)&Kp, g_K);
    cudaGetSymbolAddress((void**)&Vp, g_V);
    cudaGetSymbolAddress((void**)&Cp, g_Ctx);

    dim3 ggrid(HID/128, NROWS/128);   // 32 x 32

    gemm_nt<<<ggrid, 256>>>(hs, Wq, Qp, 1);
    gemm_nt<<<ggrid, 256>>>(hs, Wk, Kp, 1);
    gemm_nt<<<ggrid, 256>>>(hs, Wv, Vp, 1);

    rope_table_kernel<<<(S_LEN*64)/256, 256>>>(pos);
    rope_apply_kernel<<<(BATCH*HEADS*S_LEN*64)/256, 256>>>();

    size_t smem = (size_t)AT_SMEM_FLOATS * sizeof(float);   // ~117 KB
    cudaFuncSetAttribute(attn_kernel, cudaFuncAttributeMaxDynamicSharedMemorySize, (int)smem);
    attn_kernel<<<dim3(S_LEN/64, HEADS, BATCH), 256, smem>>>(Qp, Kp, Vp, Cp);

    gemm_nt<<<ggrid, 256>>>(Cp, Wo, out, 0);
}

// round 5
// speedup vs baseline: 2.6050x; 2.6050x over previous
#include <cuda_runtime.h>
#include <cuda_bf16.h>
#include <math.h>
#include <cstdint>

#define HEADS 32
#define S_LEN 2048
#define BATCH 2
#define HID   4096
#define DH    128
#define NROWS (BATCH*S_LEN)   // 4096

// ---------------- scratch (static __device__, no allocs) ----------------
__device__ float g_Q[(size_t)BATCH*HEADS*S_LEN*DH];   // 64 MB
__device__ float g_K[(size_t)BATCH*HEADS*S_LEN*DH];   // 64 MB
__device__ float g_V[(size_t)BATCH*HEADS*S_LEN*DH];   // 64 MB
__device__ float g_Ctx[(size_t)NROWS*HID];            // 64 MB
__device__ float g_cos[S_LEN*64];
__device__ float g_sin[S_LEN*64];

// bf16 hi/lo split copies
__device__ __nv_bfloat16 g_hsH[(size_t)NROWS*HID],  g_hsL[(size_t)NROWS*HID];
__device__ __nv_bfloat16 g_WqH[(size_t)HID*HID],    g_WqL[(size_t)HID*HID];
__device__ __nv_bfloat16 g_WkH[(size_t)HID*HID],    g_WkL[(size_t)HID*HID];
__device__ __nv_bfloat16 g_WvH[(size_t)HID*HID],    g_WvL[(size_t)HID*HID];
__device__ __nv_bfloat16 g_WoH[(size_t)HID*HID],    g_WoL[(size_t)HID*HID];
__device__ __nv_bfloat16 g_CtxH[(size_t)NROWS*HID], g_CtxL[(size_t)NROWS*HID];

// ---------------- helpers (compute_103-safe PTX only) ----------------
__device__ __forceinline__ uint32_t smem_u32(const void* p) {
    uint32_t a;
    asm("{ .reg .u64 t; cvta.to.shared.u64 t, %1; cvt.u32.u64 %0, t; }" : "=r"(a) : "l"(p));
    return a;
}
#define CP16(dst, src)    asm volatile("cp.async.cg.shared.global [%0], [%1], 16;" :: "r"(dst), "l"(src) : "memory")
#define CP_COMMIT()       asm volatile("cp.async.commit_group;" ::: "memory")
#define CP_WAIT(n)        asm volatile("cp.async.wait_group %0;" :: "n"(n) : "memory")

#define LDSM_X4(r0,r1,r2,r3,a) \
    asm volatile("ldmatrix.sync.aligned.m8n8.x4.shared.b16 {%0,%1,%2,%3}, [%4];" \
        : "=r"(r0),"=r"(r1),"=r"(r2),"=r"(r3) : "r"(a))

#define MMA16816(d, a, b) \
    asm volatile("mma.sync.aligned.m16n8k16.row.col.f32.bf16.bf16.f32 " \
        "{%0,%1,%2,%3}, {%4,%5,%6,%7}, {%8,%9}, {%0,%1,%2,%3};" \
        : "+f"((d)[0]),"+f"((d)[1]),"+f"((d)[2]),"+f"((d)[3]) \
        : "r"((a)[0]),"r"((a)[1]),"r"((a)[2]),"r"((a)[3]), "r"((b)[0]),"r"((b)[1]))

#define SWZ128(x) ((x) ^ (((x) >> 3) & 0x70))

// ---------------- fp32 -> bf16 hi/lo split ----------------
__global__ void split_bf16_kernel(const float* __restrict__ src,
                                  __nv_bfloat16* __restrict__ hi,
                                  __nv_bfloat16* __restrict__ lo)
{
    int i = (blockIdx.x*blockDim.x + threadIdx.x) * 4;
    float4 v = *(const float4*)(src + i);
    __nv_bfloat16 h0 = __float2bfloat16(v.x), h1 = __float2bfloat16(v.y);
    __nv_bfloat16 h2 = __float2bfloat16(v.z), h3 = __float2bfloat16(v.w);
    __nv_bfloat162 H0 = {h0, h1}, H1 = {h2, h3};
    __nv_bfloat162 L0 = {__float2bfloat16(v.x - __bfloat162float(h0)),
                         __float2bfloat16(v.y - __bfloat162float(h1))};
    __nv_bfloat162 L1 = {__float2bfloat16(v.z - __bfloat162float(h2)),
                         __float2bfloat16(v.w - __bfloat162float(h3))};
    *(__nv_bfloat162*)(hi + i)     = H0;
    *(__nv_bfloat162*)(hi + i + 2) = H1;
    *(__nv_bfloat162*)(lo + i)     = L0;
    *(__nv_bfloat162*)(lo + i + 2) = L1;
}

// ---------------- HMMA GEMM: C[M,N] = A @ B^T (A,B k-major bf16 hi/lo) ----
// 128x128 CTA tile, 8 warps (64x32 each), K chunk = 64 (128B rows, SW128),
// cp.async double-buffered. 3-product split: AhBh + AhBl + AlBh.
#define GT_STAGE_BYTES 65536   // 4 tiles x 16 KB
#define GT_SMEM_TOTAL  (2*GT_STAGE_BYTES)

__global__ __launch_bounds__(256, 1) void gemm_mma(
    const __nv_bfloat16* __restrict__ Ah, const __nv_bfloat16* __restrict__ Al,
    const __nv_bfloat16* __restrict__ Bh, const __nv_bfloat16* __restrict__ Bl,
    float* __restrict__ C, int splitHeads)
{
    extern __shared__ char smem[];
    const uint32_t sb = smem_u32(smem);
    const int tid = threadIdx.x, wid = tid >> 5, lid = tid & 31;
    const int bm = blockIdx.y * 128, bn = blockIdx.x * 128;
    const int wm = (wid >> 2) * 64, wn = (wid & 3) * 32;

    const char* aH = (const char*)Ah + (size_t)bm * (HID*2);
    const char* aL = (const char*)Al + (size_t)bm * (HID*2);
    const char* bH = (const char*)Bh + (size_t)bn * (HID*2);
    const char* bL = (const char*)Bl + (size_t)bn * (HID*2);

    int srow[4], scol[4];
    #pragma unroll
    for (int j = 0; j < 4; j++) {
        int sidx = j*256 + tid;
        srow[j] = sidx >> 3;
        scol[j] = (sidx & 7) * 16;
    }

    auto load_chunk = [&](int stage, int chunk) {
        uint32_t st = sb + stage * GT_STAGE_BYTES;
        size_t off = (size_t)chunk * 128;   // byte offset within k-row
        #pragma unroll
        for (int j = 0; j < 4; j++) {
            uint32_t d = SWZ128((uint32_t)(srow[j]*128 + scol[j]));
            size_t g = (size_t)srow[j] * (HID*2) + off + scol[j];
            CP16(st +     0 + d, aH + g);
            CP16(st + 16384 + d, aL + g);
            CP16(st + 32768 + d, bH + g);
            CP16(st + 49152 + d, bL + g);
        }
    };

    float acc[4][4][4];
    #pragma unroll
    for (int i = 0; i < 4; i++)
        #pragma unroll
        for (int j = 0; j < 4; j++)
            #pragma unroll
            for (int c = 0; c < 4; c++) acc[i][j][c] = 0.f;

    // lane roles for ldmatrix address supply
    const int q  = lid >> 3;   // 0..3 (matrix index)
    const int r8 = lid & 7;    // row within 8x8

    load_chunk(0, 0);
    CP_COMMIT();

    const int NCHUNK = HID / 64;   // 64
    for (int chunk = 0; chunk < NCHUNK; chunk++) {
        int buf = chunk & 1;
        if (chunk + 1 < NCHUNK) {
            load_chunk(buf ^ 1, chunk + 1);
            CP_COMMIT();
            CP_WAIT(1);
        } else {
            CP_WAIT(0);
        }
        __syncthreads();

        uint32_t stA = sb + buf * GT_STAGE_BYTES;
        uint32_t stAl = stA + 16384, stBh = stA + 32768, stBl = stA + 49152;

        #pragma unroll
        for (int kk = 0; kk < 4; kk++) {
            uint32_t ah[16], al[16], bh[8], bl[8];
            // A fragments: 4 m16 tiles
            #pragma unroll
            for (int i = 0; i < 4; i++) {
                int rowA = wm + i*16 + (q & 1)*8 + r8;
                int kb   = kk*32 + (q >> 1)*16;
                uint32_t off = SWZ128((uint32_t)(rowA*128 + kb));
                LDSM_X4(ah[i*4+0], ah[i*4+1], ah[i*4+2], ah[i*4+3], stA  + off);
                LDSM_X4(al[i*4+0], al[i*4+1], al[i*4+2], al[i*4+3], stAl + off);
            }
            // B fragments: 2 x (16 n-rows) -> 4 n8 tiles
            #pragma unroll
            for (int j2 = 0; j2 < 2; j2++) {
                int rowB = wn + j2*16 + (q >> 1)*8 + r8;
                int kb   = kk*32 + (q & 1)*16;
                uint32_t off = SWZ128((uint32_t)(rowB*128 + kb));
                uint32_t h0,h1,h2,h3, l0,l1,l2,l3;
                LDSM_X4(h0,h1,h2,h3, stBh + off);
                LDSM_X4(l0,l1,l2,l3, stBl + off);
                bh[j2*4+0]=h0; bh[j2*4+1]=h1; bh[j2*4+2]=h2; bh[j2*4+3]=h3;
                bl[j2*4+0]=l0; bl[j2*4+1]=l1; bl[j2*4+2]=l2; bl[j2*4+3]=l3;
            }
            #pragma unroll
            for (int i = 0; i < 4; i++)
                #pragma unroll
                for (int j = 0; j < 4; j++) {
                    MMA16816(acc[i][j], &ah[i*4], &bh[j*2]);
                    MMA16816(acc[i][j], &ah[i*4], &bl[j*2]);
                    MMA16816(acc[i][j], &al[i*4], &bh[j*2]);
                }
        }
        __syncthreads();
    }

    // ---- epilogue ----
    const int gr = lid >> 2;          // row-in-tile group
    const int gc = (lid & 3) * 2;     // col pair
    #pragma unroll
    for (int i = 0; i < 4; i++) {
        #pragma unroll
        for (int half = 0; half < 2; half++) {
            int row = bm + wm + i*16 + gr + half*8;
            #pragma unroll
            for (int j = 0; j < 4; j++) {
                int col = wn + j*8 + gc;     // 0..127 within N tile
                float2 v = half ? make_float2(acc[i][j][2], acc[i][j][3])
                                : make_float2(acc[i][j][0], acc[i][j][1]);
                float* op;
                if (splitHeads) {
                    int b = row >> 11, s = row & (S_LEN-1);
                    int h = blockIdx.x;          // 128-wide N tile == one head
                    op = C + ((((size_t)(b*HEADS + h))*S_LEN + s) << 7) + col;
                } else {
                    op = C + (size_t)row * HID + bn + col;
                }
                *(float2*)op = v;
            }
        }
    }
}

// ---------------- RoPE ----------------
__global__ void rope_table_kernel(const int* __restrict__ pos_ids)
{
    int idx = blockIdx.x*blockDim.x + threadIdx.x;
    int i = idx & 63;
    int s = idx >> 6;
    float pos = (float)pos_ids[s];
    double invf = pow(10000.0, -(double)(2*i) / 128.0);
    float ang = pos * (float)invf;
    float sn, cs;
    sincosf(ang, &sn, &cs);
    g_cos[idx] = cs;
    g_sin[idx] = sn;
}

__global__ void rope_apply_kernel()
{
    int idx = blockIdx.x*blockDim.x + threadIdx.x;
    int i  = idx & 63;
    int s  = (idx >> 6) & (S_LEN-1);
    int bh = idx >> 17;
    float cs = g_cos[(s<<6) + i];
    float sn = g_sin[(s<<6) + i];
    size_t base = (((size_t)bh * S_LEN + s) << 7) + i;
    float q0 = g_Q[base], q1 = g_Q[base+64];
    g_Q[base]    = q0*cs - q1*sn;
    g_Q[base+64] = q1*cs + q0*sn;
    float k0 = g_K[base], k1 = g_K[base+64];
    g_K[base]    = k0*cs - k1*sn;
    g_K[base+64] = k1*cs + k0*sn;
}

// ---------------- Flash attention (fp32, causal) ----------------
#define AT_SMEM_FLOATS (2*DH*68 + 64*DH + 64*68)

__global__ __launch_bounds__(256, 1) void attn_kernel(
    const float* __restrict__ Q, const float* __restrict__ Km,
    const float* __restrict__ V, float* __restrict__ Out)
{
    extern __shared__ float smf[];
    float* Qt = smf;                 // [128][68]
    float* Kt = Qt + DH*68;          // [128][68]
    float* Vs = Kt + DH*68;          // [64][128]
    float* Ps = Vs + 64*DH;          // [64][68]

    const int qt = blockIdx.x, h = blockIdx.y, b = blockIdx.z;
    const int t  = threadIdx.x;
    const int tx = t & 15, ty = t >> 4;
    const size_t bh = (size_t)b*HEADS + h;

    const float* Qg = Q + (bh*S_LEN + (size_t)qt*64)*DH;
    #pragma unroll
    for (int p = 0; p < 32; p++) {
        int e = p*256 + t;
        Qt[(e & 127)*68 + (e >> 7)] = Qg[e];
    }

    float m_i[4], l_i[4], o[4][8];
    #pragma unroll
    for (int i = 0; i < 4; i++) {
        m_i[i] = -1e30f; l_i[i] = 0.f;
        #pragma unroll
        for (int j = 0; j < 8; j++) o[i][j] = 0.f;
    }

    for (int kt = 0; kt <= qt; kt++) {
        const float* Kg = Km + (bh*S_LEN + (size_t)kt*64)*DH;
        const float* Vg = V  + (bh*S_LEN + (size_t)kt*64)*DH;
        __syncthreads();
        #pragma unroll
        for (int p = 0; p < 32; p++) {
            int e = p*256 + t;
            Kt[(e & 127)*68 + (e >> 7)] = Kg[e];
        }
        {
            const float4* Vg4 = (const float4*)Vg;
            float4* Vs4 = (float4*)Vs;
            #pragma unroll
            for (int p = 0; p < 8; p++)
                Vs4[p*256 + t] = Vg4[p*256 + t];
        }
        __syncthreads();

        float sacc[4][4];
        #pragma unroll
        for (int i = 0; i < 4; i++)
            #pragma unroll
            for (int j = 0; j < 4; j++) sacc[i][j] = 0.f;

        #pragma unroll 8
        for (int kk = 0; kk < DH; kk++) {
            float4 qv = *(const float4*)&Qt[kk*68 + ty*4];
            float4 kv = *(const float4*)&Kt[kk*68 + tx*4];
            float qa[4] = {qv.x,qv.y,qv.z,qv.w};
            float ka[4] = {kv.x,kv.y,kv.z,kv.w};
            #pragma unroll
            for (int i = 0; i < 4; i++)
                #pragma unroll
                for (int j = 0; j < 4; j++)
                    sacc[i][j] += qa[i]*ka[j];
        }

        const float scale = 0.08838834764831845f;
        const bool diag = (kt == qt);
        #pragma unroll
        for (int i = 0; i < 4; i++) {
            int r = ty*4 + i;
            float mx = -1e30f;
            #pragma unroll
            for (int j = 0; j < 4; j++) {
                float sv = sacc[i][j]*scale;
                if (diag && (tx*4 + j > r)) sv = -1e30f;
                sacc[i][j] = sv;
                mx = fmaxf(mx, sv);
            }
            mx = fmaxf(mx, __shfl_xor_sync(0xffffffffu, mx, 1));
            mx = fmaxf(mx, __shfl_xor_sync(0xffffffffu, mx, 2));
            mx = fmaxf(mx, __shfl_xor_sync(0xffffffffu, mx, 4));
            mx = fmaxf(mx, __shfl_xor_sync(0xffffffffu, mx, 8));
            float mnew = fmaxf(m_i[i], mx);
            float corr = __expf(m_i[i] - mnew);
            m_i[i] = mnew;
            float sum = 0.f;
            #pragma unroll
            for (int j = 0; j < 4; j++) {
                float pv = __expf(sacc[i][j] - mnew);
                Ps[r*68 + tx*4 + j] = pv;
                sum += pv;
            }
            sum += __shfl_xor_sync(0xffffffffu, sum, 1);
            sum += __shfl_xor_sync(0xffffffffu, sum, 2);
            sum += __shfl_xor_sync(0xffffffffu, sum, 4);
            sum += __shfl_xor_sync(0xffffffffu, sum, 8);
            l_i[i] = l_i[i]*corr + sum;
            #pragma unroll
            for (int jj = 0; jj < 8; jj++) o[i][jj] *= corr;
        }
        __syncthreads();

        #pragma unroll 4
        for (int j = 0; j < 64; j++) {
            float4 v0 = *(const float4*)&Vs[j*DH + tx*8];
            float4 v1 = *(const float4*)&Vs[j*DH + tx*8 + 4];
            #pragma unroll
            for (int i = 0; i < 4; i++) {
                float pv = Ps[(ty*4+i)*68 + j];
                o[i][0] += pv*v0.x; o[i][1] += pv*v0.y;
                o[i][2] += pv*v0.z; o[i][3] += pv*v0.w;
                o[i][4] += pv*v1.x; o[i][5] += pv*v1.y;
                o[i][6] += pv*v1.z; o[i][7] += pv*v1.w;
            }
        }
    }

    #pragma unroll
    for (int i = 0; i < 4; i++) {
        float inv = 1.0f / l_i[i];
        int srow = qt*64 + ty*4 + i;
        float* op = Out + ((size_t)b*S_LEN + srow)*HID + h*DH + tx*8;
        float4 r0 = make_float4(o[i][0]*inv, o[i][1]*inv, o[i][2]*inv, o[i][3]*inv);
        float4 r1 = make_float4(o[i][4]*inv, o[i][5]*inv, o[i][6]*inv, o[i][7]*inv);
        *(float4*)op     = r0;
        *(float4*)(op+4) = r1;
    }
}

// ---------------- launch ----------------
extern "C" void kernel_launch(void* const* d_in, const int* in_sizes, int n_in,
                              void* d_out, int out_size)
{
    const float* hs = (const float*)d_in[0];
    const float* Wq = (const float*)d_in[1];
    const float* Wk = (const float*)d_in[2];
    const float* Wv = (const float*)d_in[3];
    const float* Wo = (const float*)d_in[4];
    const int* pos  = (const int*)d_in[6];
    float* out = (float*)d_out;

    float *Qp, *Kp, *Vp, *Cp;
    cudaGetSymbolAddress((void**)&Qp, g_Q);
    cudaGetSymbolAddress((void**)&Kp, g_K);
    cudaGetSymbolAddress((void**)&Vp, g_V);
    cudaGetSymbolAddress((void**)&Cp, g_Ctx);

    __nv_bfloat16 *hsH,*hsL,*WqH,*WqL,*WkH,*WkL,*WvH,*WvL,*WoH,*WoL,*CtxH,*CtxL;
    cudaGetSymbolAddress((void**)&hsH, g_hsH);  cudaGetSymbolAddress((void**)&hsL, g_hsL);
    cudaGetSymbolAddress((void**)&WqH, g_WqH);  cudaGetSymbolAddress((void**)&WqL, g_WqL);
    cudaGetSymbolAddress((void**)&WkH, g_WkH);  cudaGetSymbolAddress((void**)&WkL, g_WkL);
    cudaGetSymbolAddress((void**)&WvH, g_WvH);  cudaGetSymbolAddress((void**)&WvL, g_WvL);
    cudaGetSymbolAddress((void**)&WoH, g_WoH);  cudaGetSymbolAddress((void**)&WoL, g_WoL);
    cudaGetSymbolAddress((void**)&CtxH, g_CtxH);cudaGetSymbolAddress((void**)&CtxL, g_CtxL);

    const int NELEM = NROWS*HID;           // = HID*HID = 16M
    const int SPLIT_BLOCKS = NELEM/4/256;

    split_bf16_kernel<<<SPLIT_BLOCKS, 256>>>(hs, hsH, hsL);
    split_bf16_kernel<<<SPLIT_BLOCKS, 256>>>(Wq, WqH, WqL);
    split_bf16_kernel<<<SPLIT_BLOCKS, 256>>>(Wk, WkH, WkL);
    split_bf16_kernel<<<SPLIT_BLOCKS, 256>>>(Wv, WvH, WvL);
    split_bf16_kernel<<<SPLIT_BLOCKS, 256>>>(Wo, WoH, WoL);

    cudaFuncSetAttribute(gemm_mma, cudaFuncAttributeMaxDynamicSharedMemorySize, GT_SMEM_TOTAL);
    dim3 ggrid(HID/128, NROWS/128);   // 32 x 32

    gemm_mma<<<ggrid, 256, GT_SMEM_TOTAL>>>(hsH, hsL, WqH, WqL, Qp, 1);
    gemm_mma<<<ggrid, 256, GT_SMEM_TOTAL>>>(hsH, hsL, WkH, WkL, Kp, 1);
    gemm_mma<<<ggrid, 256, GT_SMEM_TOTAL>>>(hsH, hsL, WvH, WvL, Vp, 1);

    rope_table_kernel<<<(S_LEN*64)/256, 256>>>(pos);
    rope_apply_kernel<<<(BATCH*HEADS*S_LEN*64)/256, 256>>>();

    size_t smem = (size_t)AT_SMEM_FLOATS * sizeof(float);   // ~117 KB
    cudaFuncSetAttribute(attn_kernel, cudaFuncAttributeMaxDynamicSharedMemorySize, (int)smem);
    attn_kernel<<<dim3(S_LEN/64, HEADS, BATCH), 256, smem>>>(Qp, Kp, Vp, Cp);

    split_bf16_kernel<<<SPLIT_BLOCKS, 256>>>(Cp, CtxH, CtxL);
    gemm_mma<<<ggrid, 256, GT_SMEM_TOTAL>>>(CtxH, CtxL, WoH, WoL, out, 0);
}

// round 6
// speedup vs baseline: 3.6983x; 1.4197x over previous
#include <cuda_runtime.h>
#include <cuda_bf16.h>
#include <math.h>
#include <cstdint>

#define HEADS 32
#define S_LEN 2048
#define BATCH 2
#define HID   4096
#define DH    128
#define NROWS (BATCH*S_LEN)   // 4096
#define NBH   (BATCH*HEADS)   // 64

// ---------------- scratch (static __device__, no allocs) ----------------
__device__ float g_Q[(size_t)NBH*S_LEN*DH];           // 64 MB fp32 (pre-rope)
__device__ float g_K[(size_t)NBH*S_LEN*DH];
__device__ float g_V[(size_t)NBH*S_LEN*DH];
__device__ float g_Ctx[(size_t)NROWS*HID];
__device__ float g_cos[S_LEN*64];
__device__ float g_sin[S_LEN*64];

// bf16 hi/lo splits
__device__ __nv_bfloat16 g_hsH[(size_t)NROWS*HID],  g_hsL[(size_t)NROWS*HID];
__device__ __nv_bfloat16 g_WqH[(size_t)HID*HID],    g_WqL[(size_t)HID*HID];
__device__ __nv_bfloat16 g_WkH[(size_t)HID*HID],    g_WkL[(size_t)HID*HID];
__device__ __nv_bfloat16 g_WvH[(size_t)HID*HID],    g_WvL[(size_t)HID*HID];
__device__ __nv_bfloat16 g_WoH[(size_t)HID*HID],    g_WoL[(size_t)HID*HID];
__device__ __nv_bfloat16 g_CtxH[(size_t)NROWS*HID], g_CtxL[(size_t)NROWS*HID];
// attention operands (bf16 hi/lo)
__device__ __nv_bfloat16 g_QH[(size_t)NBH*S_LEN*DH], g_QL[(size_t)NBH*S_LEN*DH];
__device__ __nv_bfloat16 g_KH[(size_t)NBH*S_LEN*DH], g_KL[(size_t)NBH*S_LEN*DH];
__device__ __nv_bfloat16 g_VtH[(size_t)NBH*DH*S_LEN], g_VtL[(size_t)NBH*DH*S_LEN]; // [bh][dh][s]

// ---------------- helpers (compute_103-safe PTX only) ----------------
__device__ __forceinline__ uint32_t smem_u32(const void* p) {
    uint32_t a;
    asm("{ .reg .u64 t; cvta.to.shared.u64 t, %1; cvt.u32.u64 %0, t; }" : "=r"(a) : "l"(p));
    return a;
}
#define CP16(dst, src)    asm volatile("cp.async.cg.shared.global [%0], [%1], 16;" :: "r"(dst), "l"(src) : "memory")
#define CP_COMMIT()       asm volatile("cp.async.commit_group;" ::: "memory")
#define CP_WAIT(n)        asm volatile("cp.async.wait_group %0;" :: "n"(n) : "memory")

#define LDSM_X4(r0,r1,r2,r3,a) \
    asm volatile("ldmatrix.sync.aligned.m8n8.x4.shared.b16 {%0,%1,%2,%3}, [%4];" \
        : "=r"(r0),"=r"(r1),"=r"(r2),"=r"(r3) : "r"(a))

#define MMA16816(d, a, b) \
    asm volatile("mma.sync.aligned.m16n8k16.row.col.f32.bf16.bf16.f32 " \
        "{%0,%1,%2,%3}, {%4,%5,%6,%7}, {%8,%9}, {%0,%1,%2,%3};" \
        : "+f"((d)[0]),"+f"((d)[1]),"+f"((d)[2]),"+f"((d)[3]) \
        : "r"((a)[0]),"r"((a)[1]),"r"((a)[2]),"r"((a)[3]), "r"((b)[0]),"r"((b)[1]))

#define SWZ128(x) ((x) ^ (((x) >> 3) & 0x70))

__device__ __forceinline__ uint32_t packbf(float lo, float hi) {
    uint32_t r;   // first src operand -> high half
    asm("cvt.rn.bf16x2.f32 %0, %1, %2;" : "=r"(r) : "f"(hi), "f"(lo));
    return r;
}

// ---------------- fp32 -> bf16 hi/lo split ----------------
__global__ void split_bf16_kernel(const float* __restrict__ src,
                                  __nv_bfloat16* __restrict__ hi,
                                  __nv_bfloat16* __restrict__ lo)
{
    int i = (blockIdx.x*blockDim.x + threadIdx.x) * 4;
    float4 v = *(const float4*)(src + i);
    __nv_bfloat16 h0 = __float2bfloat16(v.x), h1 = __float2bfloat16(v.y);
    __nv_bfloat16 h2 = __float2bfloat16(v.z), h3 = __float2bfloat16(v.w);
    __nv_bfloat162 H0 = {h0, h1}, H1 = {h2, h3};
    __nv_bfloat162 L0 = {__float2bfloat16(v.x - __bfloat162float(h0)),
                         __float2bfloat16(v.y - __bfloat162float(h1))};
    __nv_bfloat162 L1 = {__float2bfloat16(v.z - __bfloat162float(h2)),
                         __float2bfloat16(v.w - __bfloat162float(h3))};
    *(__nv_bfloat162*)(hi + i)     = H0;
    *(__nv_bfloat162*)(hi + i + 2) = H1;
    *(__nv_bfloat162*)(lo + i)     = L0;
    *(__nv_bfloat162*)(lo + i + 2) = L1;
}

// ---------------- HMMA GEMM (unchanged, verified) ----------------
#define GT_STAGE_BYTES 65536
#define GT_SMEM_TOTAL  (2*GT_STAGE_BYTES)

__global__ __launch_bounds__(256, 1) void gemm_mma(
    const __nv_bfloat16* __restrict__ Ah, const __nv_bfloat16* __restrict__ Al,
    const __nv_bfloat16* __restrict__ Bh, const __nv_bfloat16* __restrict__ Bl,
    float* __restrict__ C, int splitHeads)
{
    extern __shared__ char smem[];
    const uint32_t sb = smem_u32(smem);
    const int tid = threadIdx.x, wid = tid >> 5, lid = tid & 31;
    const int bm = blockIdx.y * 128, bn = blockIdx.x * 128;
    const int wm = (wid >> 2) * 64, wn = (wid & 3) * 32;

    const char* aH = (const char*)Ah + (size_t)bm * (HID*2);
    const char* aL = (const char*)Al + (size_t)bm * (HID*2);
    const char* bH = (const char*)Bh + (size_t)bn * (HID*2);
    const char* bL = (const char*)Bl + (size_t)bn * (HID*2);

    int srow[4], scol[4];
    #pragma unroll
    for (int j = 0; j < 4; j++) {
        int sidx = j*256 + tid;
        srow[j] = sidx >> 3;
        scol[j] = (sidx & 7) * 16;
    }

    auto load_chunk = [&](int stage, int chunk) {
        uint32_t st = sb + stage * GT_STAGE_BYTES;
        size_t off = (size_t)chunk * 128;
        #pragma unroll
        for (int j = 0; j < 4; j++) {
            uint32_t d = SWZ128((uint32_t)(srow[j]*128 + scol[j]));
            size_t g = (size_t)srow[j] * (HID*2) + off + scol[j];
            CP16(st +     0 + d, aH + g);
            CP16(st + 16384 + d, aL + g);
            CP16(st + 32768 + d, bH + g);
            CP16(st + 49152 + d, bL + g);
        }
    };

    float acc[4][4][4];
    #pragma unroll
    for (int i = 0; i < 4; i++)
        #pragma unroll
        for (int j = 0; j < 4; j++)
            #pragma unroll
            for (int c = 0; c < 4; c++) acc[i][j][c] = 0.f;

    const int q  = lid >> 3;
    const int r8 = lid & 7;

    load_chunk(0, 0);
    CP_COMMIT();

    const int NCHUNK = HID / 64;
    for (int chunk = 0; chunk < NCHUNK; chunk++) {
        int buf = chunk & 1;
        if (chunk + 1 < NCHUNK) {
            load_chunk(buf ^ 1, chunk + 1);
            CP_COMMIT();
            CP_WAIT(1);
        } else {
            CP_WAIT(0);
        }
        __syncthreads();

        uint32_t stA = sb + buf * GT_STAGE_BYTES;
        uint32_t stAl = stA + 16384, stBh = stA + 32768, stBl = stA + 49152;

        #pragma unroll
        for (int kk = 0; kk < 4; kk++) {
            uint32_t ah[16], al[16], bh[8], bl[8];
            #pragma unroll
            for (int i = 0; i < 4; i++) {
                int rowA = wm + i*16 + (q & 1)*8 + r8;
                int kb   = kk*32 + (q >> 1)*16;
                uint32_t off = SWZ128((uint32_t)(rowA*128 + kb));
                LDSM_X4(ah[i*4+0], ah[i*4+1], ah[i*4+2], ah[i*4+3], stA  + off);
                LDSM_X4(al[i*4+0], al[i*4+1], al[i*4+2], al[i*4+3], stAl + off);
            }
            #pragma unroll
            for (int j2 = 0; j2 < 2; j2++) {
                int rowB = wn + j2*16 + (q >> 1)*8 + r8;
                int kb   = kk*32 + (q & 1)*16;
                uint32_t off = SWZ128((uint32_t)(rowB*128 + kb));
                uint32_t h0,h1,h2,h3, l0,l1,l2,l3;
                LDSM_X4(h0,h1,h2,h3, stBh + off);
                LDSM_X4(l0,l1,l2,l3, stBl + off);
                bh[j2*4+0]=h0; bh[j2*4+1]=h1; bh[j2*4+2]=h2; bh[j2*4+3]=h3;
                bl[j2*4+0]=l0; bl[j2*4+1]=l1; bl[j2*4+2]=l2; bl[j2*4+3]=l3;
            }
            #pragma unroll
            for (int i = 0; i < 4; i++)
                #pragma unroll
                for (int j = 0; j < 4; j++) {
                    MMA16816(acc[i][j], &ah[i*4], &bh[j*2]);
                    MMA16816(acc[i][j], &ah[i*4], &bl[j*2]);
                    MMA16816(acc[i][j], &al[i*4], &bh[j*2]);
                }
        }
        __syncthreads();
    }

    const int gr = lid >> 2;
    const int gc = (lid & 3) * 2;
    #pragma unroll
    for (int i = 0; i < 4; i++) {
        #pragma unroll
        for (int half = 0; half < 2; half++) {
            int row = bm + wm + i*16 + gr + half*8;
            #pragma unroll
            for (int j = 0; j < 4; j++) {
                int col = wn + j*8 + gc;
                float2 v = half ? make_float2(acc[i][j][2], acc[i][j][3])
                                : make_float2(acc[i][j][0], acc[i][j][1]);
                float* op;
                if (splitHeads) {
                    int b = row >> 11, s = row & (S_LEN-1);
                    int h = blockIdx.x;
                    op = C + ((((size_t)(b*HEADS + h))*S_LEN + s) << 7) + col;
                } else {
                    op = C + (size_t)row * HID + bn + col;
                }
                *(float2*)op = v;
            }
        }
    }
}

// ---------------- RoPE ----------------
__global__ void rope_table_kernel(const int* __restrict__ pos_ids)
{
    int idx = blockIdx.x*blockDim.x + threadIdx.x;
    int i = idx & 63;
    int s = idx >> 6;
    float pos = (float)pos_ids[s];
    double invf = pow(10000.0, -(double)(2*i) / 128.0);
    float ang = pos * (float)invf;
    float sn, cs;
    sincosf(ang, &sn, &cs);
    g_cos[idx] = cs;
    g_sin[idx] = sn;
}

// rope + split to bf16 hi/lo in one pass
__global__ void rope_apply_split_kernel()
{
    int idx = blockIdx.x*blockDim.x + threadIdx.x;   // 0 .. NBH*S*64-1
    int i  = idx & 63;
    int s  = (idx >> 6) & (S_LEN-1);
    int bh = idx >> 17;
    float cs = g_cos[(s<<6) + i];
    float sn = g_sin[(s<<6) + i];
    size_t base = (((size_t)bh * S_LEN + s) << 7) + i;

    float q0 = g_Q[base], q1 = g_Q[base+64];
    float qa = q0*cs - q1*sn;
    float qb = q1*cs + q0*sn;
    __nv_bfloat16 h;
    h = __float2bfloat16(qa); g_QH[base]    = h; g_QL[base]    = __float2bfloat16(qa - __bfloat162float(h));
    h = __float2bfloat16(qb); g_QH[base+64] = h; g_QL[base+64] = __float2bfloat16(qb - __bfloat162float(h));

    float k0 = g_K[base], k1 = g_K[base+64];
    float ka = k0*cs - k1*sn;
    float kb = k1*cs + k0*sn;
    h = __float2bfloat16(ka); g_KH[base]    = h; g_KL[base]    = __float2bfloat16(ka - __bfloat162float(h));
    h = __float2bfloat16(kb); g_KH[base+64] = h; g_KL[base+64] = __float2bfloat16(kb - __bfloat162float(h));
}

// ---------------- V transpose + split:  g_V [bh][s][dh] -> g_Vt{H,L} [bh][dh][s]
__global__ void vt_split_kernel()
{
    __shared__ float tile[32][33];
    int xs = blockIdx.x * 32;      // s tile
    int dd = blockIdx.y * 32;      // dh tile
    int bh = blockIdx.z;
    int tx = threadIdx.x, ty = threadIdx.y;   // 32 x 8

    const float* V = g_V + ((size_t)bh * S_LEN) * DH;
    #pragma unroll
    for (int j = 0; j < 4; j++)
        tile[ty + j*8][tx] = V[(size_t)(xs + ty + j*8)*DH + dd + tx];
    __syncthreads();
    #pragma unroll
    for (int j = 0; j < 4; j++) {
        float v = tile[tx][ty + j*8];
        __nv_bfloat16 h = __float2bfloat16(v);
        size_t o = ((size_t)bh*DH + dd + ty + j*8) * S_LEN + xs + tx;
        g_VtH[o] = h;
        g_VtL[o] = __float2bfloat16(v - __bfloat162float(h));
    }
}

// ---------------- HMMA flash attention ----------------
// 128 q-rows/CTA, kv tiles of 64, 8 warps x 16 q-rows.
// smem: Q 4x16K (QHp0,QHp1,QLp0,QLp1) | 2 stages x { K 4x8K, VtH 16K, VtL 16K }
#define AT2_SMEM (65536 + 2*65536)

__global__ __launch_bounds__(256, 1) void attn_mma(float* __restrict__ Out)
{
    extern __shared__ char smem[];
    const uint32_t sb = smem_u32(smem);
    const int tid = threadIdx.x, wid = tid >> 5, lid = tid & 31;
    const int qt = blockIdx.x, h = blockIdx.y, b = blockIdx.z;
    const size_t bh = (size_t)b*HEADS + h;
    const int q  = lid >> 3;
    const int r8 = lid & 7;

    const char* qHb = (const char*)g_QH + (bh*S_LEN + (size_t)qt*128) * 256;
    const char* qLb = (const char*)g_QL + (bh*S_LEN + (size_t)qt*128) * 256;
    const char* kHb = (const char*)g_KH + bh*S_LEN*256;
    const char* kLb = (const char*)g_KL + bh*S_LEN*256;
    const char* vHb = (const char*)g_VtH + bh*DH*(size_t)S_LEN*2;   // row stride 4096B
    const char* vLb = (const char*)g_VtL + bh*DH*(size_t)S_LEN*2;

    // ---- Q load (once) ----
    #pragma unroll
    for (int it = 0; it < 8; it++) {
        int e = it*256 + tid;           // 0..2047
        int row = e >> 4, seg = e & 15;
        int panel = seg >> 3, c = seg & 7;
        uint32_t d = SWZ128((uint32_t)(row*128 + c*16));
        CP16(sb + panel*16384 + d,          qHb + row*256 + seg*16);
        CP16(sb + (2+panel)*16384 + d,      qLb + row*256 + seg*16);
    }

    auto load_kv = [&](int st, int kt) {
        uint32_t stb = sb + 65536 + st*65536;
        #pragma unroll
        for (int it = 0; it < 4; it++) {
            int e = it*256 + tid;       // 0..1023  (K: 64 rows x 16 segs)
            int row = e >> 4, seg = e & 15;
            int panel = seg >> 3, c = seg & 7;
            uint32_t d = SWZ128((uint32_t)(row*128 + c*16));
            size_t g = (size_t)(kt*64 + row)*256 + seg*16;
            CP16(stb + panel*8192 + d,         kHb + g);
            CP16(stb + 16384 + panel*8192 + d, kLb + g);
        }
        #pragma unroll
        for (int it = 0; it < 4; it++) {
            int e = it*256 + tid;       // 0..1023  (Vt: 128 rows x 8 segs)
            int row = e >> 3, c = e & 7;
            uint32_t d = SWZ128((uint32_t)(row*128 + c*16));
            size_t g = (size_t)row*4096 + (size_t)kt*128 + c*16;
            CP16(stb + 32768 + d, vHb + g);
            CP16(stb + 49152 + d, vLb + g);
        }
    };

    load_kv(0, 0);
    CP_COMMIT();

    float o[16][4];
    #pragma unroll
    for (int t = 0; t < 16; t++)
        #pragma unroll
        for (int c = 0; c < 4; c++) o[t][c] = 0.f;
    float m0 = -1e30f, m1 = -1e30f, l0 = 0.f, l1 = 0.f;

    const float scale = 0.08838834764831845f;
    const int qrow_lo = qt*128 + wid*16;
    const int row0 = qrow_lo + (lid >> 2);       // rows for d0,d1
    const int col_in = (lid & 3) * 2;

    const int nkv = 2*qt + 2;
    for (int kt = 0; kt < nkv; kt++) {
        int buf = kt & 1;
        if (kt + 1 < nkv) {
            load_kv(buf ^ 1, kt + 1);
            CP_COMMIT();
            CP_WAIT(1);
        } else {
            CP_WAIT(0);
        }
        __syncthreads();

        bool skip = (kt*64 > qrow_lo + 15);
        if (!skip) {
            uint32_t stb = sb + 65536 + buf*65536;

            // ---- S = Q K^T ----
            float sacc[8][4];
            #pragma unroll
            for (int t = 0; t < 8; t++)
                #pragma unroll
                for (int c = 0; c < 4; c++) sacc[t][c] = 0.f;

            #pragma unroll
            for (int kk = 0; kk < 8; kk++) {
                int panel = kk >> 2;
                int kb = (kk & 3)*32;
                uint32_t qh[4], ql[4];
                {
                    int rowA = wid*16 + (q & 1)*8 + r8;
                    uint32_t off = SWZ128((uint32_t)(rowA*128 + kb + (q >> 1)*16));
                    LDSM_X4(qh[0],qh[1],qh[2],qh[3], sb + panel*16384 + off);
                    LDSM_X4(ql[0],ql[1],ql[2],ql[3], sb + (2+panel)*16384 + off);
                }
                #pragma unroll
                for (int j2 = 0; j2 < 4; j2++) {
                    int rowB = j2*16 + (q >> 1)*8 + r8;
                    uint32_t off = SWZ128((uint32_t)(rowB*128 + kb + (q & 1)*16));
                    uint32_t kh[4], kl[4];
                    LDSM_X4(kh[0],kh[1],kh[2],kh[3], stb + panel*8192 + off);
                    LDSM_X4(kl[0],kl[1],kl[2],kl[3], stb + 16384 + panel*8192 + off);
                    MMA16816(sacc[j2*2],   qh, &kh[0]);
                    MMA16816(sacc[j2*2],   qh, &kl[0]);
                    MMA16816(sacc[j2*2],   ql, &kh[0]);
                    MMA16816(sacc[j2*2+1], qh, &kh[2]);
                    MMA16816(sacc[j2*2+1], qh, &kl[2]);
                    MMA16816(sacc[j2*2+1], ql, &kh[2]);
                }
            }

            // ---- scale + causal mask ----
            #pragma unroll
            for (int t = 0; t < 8; t++)
                #pragma unroll
                for (int c = 0; c < 4; c++) sacc[t][c] *= scale;

            if (kt*64 + 63 > qrow_lo) {
                #pragma unroll
                for (int t = 0; t < 8; t++) {
                    int colg = kt*64 + t*8 + col_in;
                    if (colg   > row0)   sacc[t][0] = -1e30f;
                    if (colg+1 > row0)   sacc[t][1] = -1e30f;
                    if (colg   > row0+8) sacc[t][2] = -1e30f;
                    if (colg+1 > row0+8) sacc[t][3] = -1e30f;
                }
            }

            // ---- online softmax ----
            float mx0 = -1e30f, mx1 = -1e30f;
            #pragma unroll
            for (int t = 0; t < 8; t++) {
                mx0 = fmaxf(mx0, fmaxf(sacc[t][0], sacc[t][1]));
                mx1 = fmaxf(mx1, fmaxf(sacc[t][2], sacc[t][3]));
            }
            mx0 = fmaxf(mx0, __shfl_xor_sync(0xffffffffu, mx0, 1));
            mx0 = fmaxf(mx0, __shfl_xor_sync(0xffffffffu, mx0, 2));
            mx1 = fmaxf(mx1, __shfl_xor_sync(0xffffffffu, mx1, 1));
            mx1 = fmaxf(mx1, __shfl_xor_sync(0xffffffffu, mx1, 2));
            float mn0 = fmaxf(m0, mx0), mn1 = fmaxf(m1, mx1);
            float cr0 = __expf(m0 - mn0), cr1 = __expf(m1 - mn1);
            m0 = mn0; m1 = mn1;

            float s0 = 0.f, s1 = 0.f;
            #pragma unroll
            for (int t = 0; t < 8; t++) {
                sacc[t][0] = __expf(sacc[t][0] - mn0);
                sacc[t][1] = __expf(sacc[t][1] - mn0);
                sacc[t][2] = __expf(sacc[t][2] - mn1);
                sacc[t][3] = __expf(sacc[t][3] - mn1);
                s0 += sacc[t][0] + sacc[t][1];
                s1 += sacc[t][2] + sacc[t][3];
            }
            s0 += __shfl_xor_sync(0xffffffffu, s0, 1);
            s0 += __shfl_xor_sync(0xffffffffu, s0, 2);
            s1 += __shfl_xor_sync(0xffffffffu, s1, 1);
            s1 += __shfl_xor_sync(0xffffffffu, s1, 2);
            l0 = l0*cr0 + s0;
            l1 = l1*cr1 + s1;
            #pragma unroll
            for (int t = 0; t < 16; t++) {
                o[t][0] *= cr0; o[t][1] *= cr0;
                o[t][2] *= cr1; o[t][3] *= cr1;
            }

            // ---- pack P hi/lo into A-fragments ----
            uint32_t ph[4][4], pl[4][4];
            #pragma unroll
            for (int t = 0; t < 4; t++) {
                #pragma unroll
                for (int u = 0; u < 2; u++) {        // u: tile 2t+u
                    float p00 = sacc[2*t+u][0], p01 = sacc[2*t+u][1];
                    float p10 = sacc[2*t+u][2], p11 = sacc[2*t+u][3];
                    float h00 = __bfloat162float(__float2bfloat16(p00));
                    float h01 = __bfloat162float(__float2bfloat16(p01));
                    float h10 = __bfloat162float(__float2bfloat16(p10));
                    float h11 = __bfloat162float(__float2bfloat16(p11));
                    ph[t][u*2+0] = packbf(h00, h01);
                    ph[t][u*2+1] = packbf(h10, h11);
                    pl[t][u*2+0] = packbf(p00-h00, p01-h01);
                    pl[t][u*2+1] = packbf(p10-h10, p11-h11);
                }
            }
            // reorder: a0=tile0 rows, a1=tile0 rows+8, a2=tile1 rows, a3=tile1 rows+8
            // packbf above already placed: [t][0]=t0 rows, [t][1]=t0 rows+8, [t][2]=t1 rows, [t][3]=t1 rows+8  ✓

            // ---- O += P V ----
            #pragma unroll
            for (int ks = 0; ks < 4; ks++) {
                int kb = ks*32;
                #pragma unroll
                for (int j2 = 0; j2 < 8; j2++) {
                    int rowB = j2*16 + (q >> 1)*8 + r8;
                    uint32_t off = SWZ128((uint32_t)(rowB*128 + kb + (q & 1)*16));
                    uint32_t vh[4], vl[4];
                    LDSM_X4(vh[0],vh[1],vh[2],vh[3], stb + 32768 + off);
                    LDSM_X4(vl[0],vl[1],vl[2],vl[3], stb + 49152 + off);
                    MMA16816(o[j2*2],   ph[ks], &vh[0]);
                    MMA16816(o[j2*2],   ph[ks], &vl[0]);
                    MMA16816(o[j2*2],   pl[ks], &vh[0]);
                    MMA16816(o[j2*2+1], ph[ks], &vh[2]);
                    MMA16816(o[j2*2+1], ph[ks], &vl[2]);
                    MMA16816(o[j2*2+1], pl[ks], &vh[2]);
                }
            }
        }
        __syncthreads();
    }

    // ---- normalize + write [B,S,HID] ----
    float inv0 = 1.0f / l0, inv1 = 1.0f / l1;
    float* base0 = Out + ((size_t)b*S_LEN + row0)    * HID + h*DH + col_in;
    float* base1 = Out + ((size_t)b*S_LEN + row0 + 8)* HID + h*DH + col_in;
    #pragma unroll
    for (int t = 0; t < 16; t++) {
        *(float2*)(base0 + t*8) = make_float2(o[t][0]*inv0, o[t][1]*inv0);
        *(float2*)(base1 + t*8) = make_float2(o[t][2]*inv1, o[t][3]*inv1);
    }
}

// ---------------- launch ----------------
extern "C" void kernel_launch(void* const* d_in, const int* in_sizes, int n_in,
                              void* d_out, int out_size)
{
    const float* hs = (const float*)d_in[0];
    const float* Wq = (const float*)d_in[1];
    const float* Wk = (const float*)d_in[2];
    const float* Wv = (const float*)d_in[3];
    const float* Wo = (const float*)d_in[4];
    const int* pos  = (const int*)d_in[6];
    float* out = (float*)d_out;

    float *Qp, *Kp, *Vp, *Cp;
    cudaGetSymbolAddress((void**)&Qp, g_Q);
    cudaGetSymbolAddress((void**)&Kp, g_K);
    cudaGetSymbolAddress((void**)&Vp, g_V);
    cudaGetSymbolAddress((void**)&Cp, g_Ctx);

    __nv_bfloat16 *hsH,*hsL,*WqH,*WqL,*WkH,*WkL,*WvH,*WvL,*WoH,*WoL,*CtxH,*CtxL;
    cudaGetSymbolAddress((void**)&hsH, g_hsH);  cudaGetSymbolAddress((void**)&hsL, g_hsL);
    cudaGetSymbolAddress((void**)&WqH, g_WqH);  cudaGetSymbolAddress((void**)&WqL, g_WqL);
    cudaGetSymbolAddress((void**)&WkH, g_WkH);  cudaGetSymbolAddress((void**)&WkL, g_WkL);
    cudaGetSymbolAddress((void**)&WvH, g_WvH);  cudaGetSymbolAddress((void**)&WvL, g_WvL);
    cudaGetSymbolAddress((void**)&WoH, g_WoH);  cudaGetSymbolAddress((void**)&WoL, g_WoL);
    cudaGetSymbolAddress((void**)&CtxH, g_CtxH);cudaGetSymbolAddress((void**)&CtxL, g_CtxL);

    const int NELEM = NROWS*HID;
    const int SPLIT_BLOCKS = NELEM/4/256;

    split_bf16_kernel<<<SPLIT_BLOCKS, 256>>>(hs, hsH, hsL);
    split_bf16_kernel<<<SPLIT_BLOCKS, 256>>>(Wq, WqH, WqL);
    split_bf16_kernel<<<SPLIT_BLOCKS, 256>>>(Wk, WkH, WkL);
    split_bf16_kernel<<<SPLIT_BLOCKS, 256>>>(Wv, WvH, WvL);
    split_bf16_kernel<<<SPLIT_BLOCKS, 256>>>(Wo, WoH, WoL);

    cudaFuncSetAttribute(gemm_mma, cudaFuncAttributeMaxDynamicSharedMemorySize, GT_SMEM_TOTAL);
    dim3 ggrid(HID/128, NROWS/128);

    gemm_mma<<<ggrid, 256, GT_SMEM_TOTAL>>>(hsH, hsL, WqH, WqL, Qp, 1);
    gemm_mma<<<ggrid, 256, GT_SMEM_TOTAL>>>(hsH, hsL, WkH, WkL, Kp, 1);
    gemm_mma<<<ggrid, 256, GT_SMEM_TOTAL>>>(hsH, hsL, WvH, WvL, Vp, 1);

    rope_table_kernel<<<(S_LEN*64)/256, 256>>>(pos);
    rope_apply_split_kernel<<<(NBH*S_LEN*64)/256, 256>>>();
    vt_split_kernel<<<dim3(S_LEN/32, DH/32, NBH), dim3(32,8)>>>();

    cudaFuncSetAttribute(attn_mma, cudaFuncAttributeMaxDynamicSharedMemorySize, AT2_SMEM);
    attn_mma<<<dim3(S_LEN/128, HEADS, BATCH), 256, AT2_SMEM>>>(Cp);

    split_bf16_kernel<<<SPLIT_BLOCKS, 256>>>(Cp, CtxH, CtxL);
    gemm_mma<<<ggrid, 256, GT_SMEM_TOTAL>>>(CtxH, CtxL, WoH, WoL, out, 0);
}